// round 4
// baseline (speedup 1.0000x reference)
#include <cuda_runtime.h>
#include <cuda_bf16.h>
#include <math.h>
#include <stdint.h>

// Problem constants
#define FEAT_DIM 512
#define H_DIM    512
#define DEPTH    17
#define N_NODES  ((1 << DEPTH) - 1)   // 131071
#define GATE5    (5 * H_DIM)          // 2560
#define MAX_PREV (1 << (DEPTH - 2))   // 32768

// ---------------------------------------------------------------------------
// Scratch (static __device__ allocations; no cudaMalloc allowed)
// ---------------------------------------------------------------------------
__device__ float g_iofux[(size_t)N_NODES * GATE5];
__device__ float g_px   [(size_t)N_NODES * H_DIM];
__device__ float g_c    [(size_t)N_NODES * H_DIM];
__device__ float g_hh   [(size_t)MAX_PREV * GATE5];

// ---------------------------------------------------------------------------
// Helpers
// ---------------------------------------------------------------------------
__device__ __forceinline__ uint32_t smem_u32(const void* p) {
    uint32_t a;
    asm("{ .reg .u64 t; cvta.to.shared.u64 t, %1; cvt.u32.u64 %0, t; }" : "=r"(a) : "l"(p));
    return a;
}
__device__ __forceinline__ uint32_t f2tf(float x) {
    uint32_t u; asm("cvt.rna.tf32.f32 %0, %1;" : "=r"(u) : "f"(x)); return u;
}
#define SWZ128(b) ((b) ^ (((b) >> 3) & 0x70))

#define CP_ASYNC16(dst, src) \
    asm volatile("cp.async.cg.shared.global [%0], [%1], 16;" :: "r"(dst), "l"(src) : "memory")
#define CP_COMMIT() asm volatile("cp.async.commit_group;" ::: "memory")
#define CP_WAIT2()  asm volatile("cp.async.wait_group 2;" ::: "memory")

__device__ __forceinline__ void mma_tf32(float c[4],
                                         uint32_t a0, uint32_t a1, uint32_t a2, uint32_t a3,
                                         uint32_t b0, uint32_t b1)
{
    asm volatile(
        "mma.sync.aligned.m16n8k8.row.col.f32.tf32.tf32.f32 "
        "{%0,%1,%2,%3}, {%4,%5,%6,%7}, {%8,%9}, {%0,%1,%2,%3};\n"
        : "+f"(c[0]), "+f"(c[1]), "+f"(c[2]), "+f"(c[3])
        : "r"(a0), "r"(a1), "r"(a2), "r"(a3), "r"(b0), "r"(b1));
}

// ---------------------------------------------------------------------------
// tf32 mma.sync GEMM with cp.async 3-stage pipeline.
// C[M,N] = A[M,K] @ B[N,K]^T.  K % 32 == 0, N % 128 == 0, M edge clamped.
// BM=BN=128, BK=32 (128-byte SW128-swizzled rows). 256 thr = 8 warps,
// warp tile 32x64 (2x8 m16n8k8 tiles). RNA tf32 cvt at fragment load.
// ---------------------------------------------------------------------------
#define BM 128
#define BN 128
#define BK 32
#define STAGES      3
#define STAGE_BYTES 32768          // A 16KB + B 16KB
#define OFF_A(s) ((s) * STAGE_BYTES)
#define OFF_B(s) ((s) * STAGE_BYTES + 16384)
#define SMEM_DYN (STAGES * STAGE_BYTES + 1024)   // + alignment slack

__global__ void __launch_bounds__(256, 2) tf32mma_gemm(
    const float* __restrict__ A, const float* __restrict__ B,
    float* __restrict__ C, int M, int N, int K)
{
    extern __shared__ char smem_raw[];
    char* sm = (char*)(((uintptr_t)smem_raw + 1023) & ~(uintptr_t)1023);
    const uint32_t sb = smem_u32(sm);

    const int tid  = threadIdx.x;
    const int lane = tid & 31;
    const int wid  = tid >> 5;
    const int wm   = wid & 3;        // warp row group (32 rows)
    const int wn   = wid >> 2;       // warp col group (64 cols)
    const int gid  = lane >> 2;      // 0..7
    const int tig  = lane & 3;       // 0..3
    const int bm   = blockIdx.y * BM;
    const int bn   = blockIdx.x * BN;

    // Loader mapping: chunk ci = tid + i*256; row = (tid>>3) + 32*i; f4 = tid&7
    const int lr = tid >> 3;         // 0..31
    const int f4 = tid & 7;          // 16B chunk within 128B row

    float acc[2][8][4];
#pragma unroll
    for (int mt = 0; mt < 2; mt++)
#pragma unroll
        for (int nt = 0; nt < 8; nt++)
#pragma unroll
            for (int r = 0; r < 4; r++) acc[mt][nt][r] = 0.f;

    // ---- async stage issue
    auto issue = [&](int s) {
        const int buf = s % STAGES;
        const int k0  = s * BK;
#pragma unroll
        for (int i = 0; i < 4; i++) {
            int row = lr + 32 * i;
            int gr  = bm + row; if (gr >= M) gr = M - 1;
            const float* src = A + (size_t)gr * K + k0 + f4 * 4;
            uint32_t dst = sb + OFF_A(buf) + SWZ128(row * 128 + f4 * 16);
            CP_ASYNC16(dst, src);
        }
#pragma unroll
        for (int i = 0; i < 4; i++) {
            int row = lr + 32 * i;
            const float* src = B + (size_t)(bn + row) * K + k0 + f4 * 4;
            uint32_t dst = sb + OFF_B(buf) + SWZ128(row * 128 + f4 * 16);
            CP_ASYNC16(dst, src);
        }
        CP_COMMIT();
    };

    issue(0);
    issue(1);

    const int nst = K / BK;          // 16
    for (int s = 0; s < nst; s++) {
        if (s + 2 < nst) issue(s + 2);
        else             CP_COMMIT();          // keep group count uniform
        CP_WAIT2();                            // stage s landed
        __syncthreads();

        const char* As = sm + OFF_A(s % STAGES);
        const char* Bs = sm + OFF_B(s % STAGES);

#pragma unroll
        for (int ks = 0; ks < 4; ks++) {
            const int w0 = (ks * 8 + tig) * 4;     // byte-in-row, k lo
            const int w1 = w0 + 16;                // k hi (+4 floats)

            uint32_t af[2][4];
#pragma unroll
            for (int mt = 0; mt < 2; mt++) {
                const int m0 = (wm * 32 + mt * 16 + gid) * 128;
                const int m8 = m0 + 8 * 128;
                af[mt][0] = f2tf(*(const float*)(As + SWZ128(m0 + w0)));
                af[mt][1] = f2tf(*(const float*)(As + SWZ128(m8 + w0)));
                af[mt][2] = f2tf(*(const float*)(As + SWZ128(m0 + w1)));
                af[mt][3] = f2tf(*(const float*)(As + SWZ128(m8 + w1)));
            }
            uint32_t bf[8][2];
#pragma unroll
            for (int nt = 0; nt < 8; nt++) {
                const int n0 = (wn * 64 + nt * 8 + gid) * 128;
                bf[nt][0] = f2tf(*(const float*)(Bs + SWZ128(n0 + w0)));
                bf[nt][1] = f2tf(*(const float*)(Bs + SWZ128(n0 + w1)));
            }
#pragma unroll
            for (int mt = 0; mt < 2; mt++)
#pragma unroll
                for (int nt = 0; nt < 8; nt++)
                    mma_tf32(acc[mt][nt], af[mt][0], af[mt][1], af[mt][2], af[mt][3],
                             bf[nt][0], bf[nt][1]);
        }
        __syncthreads();
    }

    // ---- Epilogue: direct float2 stores (validated mapping)
#pragma unroll
    for (int mt = 0; mt < 2; mt++) {
        int r0 = bm + wm * 32 + mt * 16 + gid;
        int r1 = r0 + 8;
#pragma unroll
        for (int nt = 0; nt < 8; nt++) {
            int col = bn + wn * 64 + nt * 8 + tig * 2;
            if (r0 < M)
                *(float2*)(C + (size_t)r0 * N + col) = make_float2(acc[mt][nt][0], acc[mt][nt][1]);
            if (r1 < M)
                *(float2*)(C + (size_t)r1 * N + col) = make_float2(acc[mt][nt][2], acc[mt][nt][3]);
        }
    }
}

// ---------------------------------------------------------------------------
// Per-level fused gate/elementwise kernel (unchanged, validated)
// ---------------------------------------------------------------------------
__device__ __forceinline__ float sigf(float x) { return 1.f / (1.f + expf(-x)); }
__device__ __forceinline__ float4 f4add(float4 a, float4 b) {
    return make_float4(a.x + b.x, a.y + b.y, a.z + b.z, a.w + b.w);
}

__global__ void __launch_bounds__(256) lstm_level_kernel(
    const float* __restrict__ iofux_b, const float* __restrict__ iofuh_b,
    const float* __restrict__ px_b, float* __restrict__ out,
    int start, int n, int hasPrev)
{
    int idx = blockIdx.x * 256 + threadIdx.x;
    int total = n * (H_DIM / 4);
    if (idx >= total) return;

    int j  = idx >> 7;
    int t4 = idx & 127;
    size_t g = (size_t)start + j;

    const float4* gx = (const float4*)(g_iofux + g * GATE5);
    float4 vi = gx[t4];
    float4 vo = gx[128 + t4];
    float4 vf = gx[256 + t4];
    float4 vu = gx[384 + t4];
    float4 vr = gx[512 + t4];

    float4 pc = make_float4(0.f, 0.f, 0.f, 0.f);
    if (hasPrev) {
        const float4* gh = (const float4*)(g_hh + (size_t)(j >> 1) * GATE5);
        vi = f4add(vi, gh[t4]);
        vo = f4add(vo, gh[128 + t4]);
        vf = f4add(vf, gh[256 + t4]);
        vu = f4add(vu, gh[384 + t4]);
        vr = f4add(vr, gh[512 + t4]);
        size_t parent = (g - 1) >> 1;
        pc = ((const float4*)g_c)[parent * 128 + t4];
    }

    const float4* bx = (const float4*)iofux_b;
    const float4* bh = (const float4*)iofuh_b;
    vi = f4add(vi, f4add(bx[t4],       bh[t4]));
    vo = f4add(vo, f4add(bx[128 + t4], bh[128 + t4]));
    vf = f4add(vf, f4add(bx[256 + t4], bh[256 + t4]));
    vu = f4add(vu, f4add(bx[384 + t4], bh[384 + t4]));
    vr = f4add(vr, f4add(bx[512 + t4], bh[512 + t4]));

    float4 px4 = f4add(((const float4*)g_px)[g * 128 + t4],
                       ((const float4*)px_b)[t4]);

    float4 c4, h4;
#define GATE(C) {                                                     \
        float i_ = sigf(vi.C); float o_ = sigf(vo.C);                 \
        float f_ = sigf(vf.C); float u_ = tanhf(vu.C);                \
        float r_ = sigf(vr.C);                                        \
        float c_ = i_ * u_ + f_ * pc.C;                               \
        float h_ = o_ * tanhf(c_);                                    \
        c4.C = c_; h4.C = r_ * h_ + (1.f - r_) * px4.C; }
    GATE(x) GATE(y) GATE(z) GATE(w)
#undef GATE

    ((float4*)g_c)[g * 128 + t4] = c4;
    ((float4*)out)[g * 128 + t4] = h4;
}

// ---------------------------------------------------------------------------
// kernel_launch
// ---------------------------------------------------------------------------
extern "C" void kernel_launch(void* const* d_in, const int* in_sizes, int n_in,
                              void* d_out, int out_size)
{
    const float* features = (const float*)d_in[0];
    const float* px_w     = (const float*)d_in[1];
    const float* px_b     = (const float*)d_in[2];
    const float* iofux_w  = (const float*)d_in[3];
    const float* iofux_b  = (const float*)d_in[4];
    const float* iofuh_w  = (const float*)d_in[5];
    const float* iofuh_b  = (const float*)d_in[6];
    float* out = (float*)d_out;

    float *iofux_p = nullptr, *px_p = nullptr, *hh_p = nullptr;
    cudaGetSymbolAddress((void**)&iofux_p, g_iofux);
    cudaGetSymbolAddress((void**)&px_p,    g_px);
    cudaGetSymbolAddress((void**)&hh_p,    g_hh);

    cudaFuncSetAttribute(tf32mma_gemm, cudaFuncAttributeMaxDynamicSharedMemorySize, SMEM_DYN);

    dim3 blk(256);

    // px = feats @ px_w.T   [N_NODES, 512]
    {
        dim3 grid(H_DIM / BN, (N_NODES + BM - 1) / BM);
        tf32mma_gemm<<<grid, blk, SMEM_DYN>>>(features, px_w, px_p, N_NODES, H_DIM, FEAT_DIM);
    }
    // iofux = feats @ iofux_w.T  [N_NODES, 2560]
    {
        dim3 grid(GATE5 / BN, (N_NODES + BM - 1) / BM);
        tf32mma_gemm<<<grid, blk, SMEM_DYN>>>(features, iofux_w, iofux_p, N_NODES, GATE5, FEAT_DIM);
    }

    for (int d = 0; d < DEPTH; d++) {
        int n = 1 << d;
        int start = n - 1;
        if (d > 0) {
            int Md = n >> 1;
            int startPrev = Md - 1;
            dim3 grid(GATE5 / BN, (Md + BM - 1) / BM);
            tf32mma_gemm<<<grid, blk, SMEM_DYN>>>(out + (size_t)startPrev * H_DIM,
                                                  iofuh_w, hh_p, Md, GATE5, FEAT_DIM);
        }
        int total = n * (H_DIM / 4);
        int nb = (total + 255) / 256;
        lstm_level_kernel<<<nb, blk>>>(iofux_b, iofuh_b, px_b, out,
                                       start, n, d > 0 ? 1 : 0);
    }
}

// round 5
// speedup vs baseline: 1.6188x; 1.6188x over previous
#include <cuda_runtime.h>
#include <cuda_fp16.h>
#include <math.h>
#include <stdint.h>

// Problem constants
#define FEAT_DIM 512
#define H_DIM    512
#define DEPTH    17
#define N_NODES  ((1 << DEPTH) - 1)   // 131071
#define GATE5    (5 * H_DIM)          // 2560
#define MAX_PREV (1 << (DEPTH - 2))   // 32768

// ---------------------------------------------------------------------------
// Scratch (static __device__ allocations; no cudaMalloc allowed)
// ---------------------------------------------------------------------------
__device__ float g_iofux[(size_t)N_NODES * GATE5];
__device__ float g_px   [(size_t)N_NODES * H_DIM];
__device__ float g_c    [(size_t)N_NODES * H_DIM];
__device__ float g_hh   [(size_t)MAX_PREV * GATE5];

// ---------------------------------------------------------------------------
// fp16 mma GEMM:  C[M,N] = A[M,K] @ B[N,K]^T,  fp32 in/out, fp32 accumulate.
// A row-major [M,K], B row-major [N,K]. K%16==0, N%128==0, M edge clamped.
// Block 128x128, BK=16 (one m16n8k16 k-step), 256 thr = 8 warps,
// warp tile 32x64 = 2x8 mma tiles. fp32 -> fp16 RN convert once at SMEM store.
// SMEM row stride 40 halfs (=20 words): same conflict profile as validated
// round-2 layout. Double-buffered SMEM: one __syncthreads per stage.
// ---------------------------------------------------------------------------
#define BM 128
#define BN 128
#define BK 16
#define LH 40    // halfs per SMEM row

__device__ __forceinline__ void mma_f16(float c[4],
                                        uint32_t a0, uint32_t a1, uint32_t a2, uint32_t a3,
                                        uint32_t b0, uint32_t b1)
{
    asm volatile(
        "mma.sync.aligned.m16n8k16.row.col.f32.f16.f16.f32 "
        "{%0,%1,%2,%3}, {%4,%5,%6,%7}, {%8,%9}, {%0,%1,%2,%3};\n"
        : "+f"(c[0]), "+f"(c[1]), "+f"(c[2]), "+f"(c[3])
        : "r"(a0), "r"(a1), "r"(a2), "r"(a3), "r"(b0), "r"(b1));
}

__device__ __forceinline__ uint32_t pack2h(float lo, float hi) {
    __half2 h = __floats2half2_rn(lo, hi);
    return *(uint32_t*)&h;
}

__global__ void __launch_bounds__(256, 2) h16gemm_tn(
    const float* __restrict__ A, const float* __restrict__ B,
    float* __restrict__ C, int M, int N, int K)
{
    __shared__ __align__(16) __half As[2][BM * LH];
    __shared__ __align__(16) __half Bs[2][BN * LH];

    const int tid  = threadIdx.x;
    const int lane = tid & 31;
    const int wid  = tid >> 5;
    const int wm   = wid & 3;        // warp row group (32 rows)
    const int wn   = wid >> 2;       // warp col group (64 cols)
    const int gid  = lane >> 2;      // 0..7
    const int tig  = lane & 3;       // 0..3
    const int bm   = blockIdx.y * BM;
    const int bn   = blockIdx.x * BN;

    // Loader: each thread owns 8 consecutive k of one row (2 float4 LDG)
    const int lrow = tid >> 1;             // 0..127
    const int lh   = (tid & 1) * 8;        // k offset 0 or 8

    int ar = bm + lrow; if (ar >= M) ar = M - 1;
    const float* Ap = A + (size_t)ar * K + lh;
    const float* Bp = B + (size_t)(bn + lrow) * K + lh;

    float acc[2][8][4];
#pragma unroll
    for (int mt = 0; mt < 2; mt++)
#pragma unroll
        for (int nt = 0; nt < 8; nt++)
#pragma unroll
            for (int r = 0; r < 4; r++) acc[mt][nt][r] = 0.f;

    // ---- prefetch + store helpers
    float4 fa0, fa1, fb0, fb1;
    auto prefetch = [&](int s) {
        const int k0 = s * BK;
        fa0 = *(const float4*)(Ap + k0);
        fa1 = *(const float4*)(Ap + k0 + 4);
        fb0 = *(const float4*)(Bp + k0);
        fb1 = *(const float4*)(Bp + k0 + 4);
    };
    auto store = [&](int b) {
        uint4 va;
        va.x = pack2h(fa0.x, fa0.y); va.y = pack2h(fa0.z, fa0.w);
        va.z = pack2h(fa1.x, fa1.y); va.w = pack2h(fa1.z, fa1.w);
        *(uint4*)&As[b][lrow * LH + lh] = va;
        uint4 vb;
        vb.x = pack2h(fb0.x, fb0.y); vb.y = pack2h(fb0.z, fb0.w);
        vb.z = pack2h(fb1.x, fb1.y); vb.w = pack2h(fb1.z, fb1.w);
        *(uint4*)&Bs[b][lrow * LH + lh] = vb;
    };

    prefetch(0);
    store(0);
    __syncthreads();

    const int nst = K / BK;          // 32
    for (int s = 0; s < nst; s++) {
        const int b = s & 1;
        if (s + 1 < nst) prefetch(s + 1);

        // one k16 step
        const __half* Ab = As[b];
        const __half* Bb = Bs[b];
        uint32_t af[2][4];
#pragma unroll
        for (int mt = 0; mt < 2; mt++) {
            const int r0 = (wm * 32 + mt * 16 + gid) * LH + tig * 2;
            af[mt][0] = *(const uint32_t*)(Ab + r0);
            af[mt][1] = *(const uint32_t*)(Ab + r0 + 8 * LH);
            af[mt][2] = *(const uint32_t*)(Ab + r0 + 8);
            af[mt][3] = *(const uint32_t*)(Ab + r0 + 8 * LH + 8);
        }
        uint32_t bf[8][2];
#pragma unroll
        for (int nt = 0; nt < 8; nt++) {
            const int n0 = (wn * 64 + nt * 8 + gid) * LH + tig * 2;
            bf[nt][0] = *(const uint32_t*)(Bb + n0);
            bf[nt][1] = *(const uint32_t*)(Bb + n0 + 8);
        }
#pragma unroll
        for (int mt = 0; mt < 2; mt++)
#pragma unroll
            for (int nt = 0; nt < 8; nt++)
                mma_f16(acc[mt][nt], af[mt][0], af[mt][1], af[mt][2], af[mt][3],
                        bf[nt][0], bf[nt][1]);

        if (s + 1 < nst) {
            store(b ^ 1);
            __syncthreads();
        }
    }

    // ---- Epilogue: validated mapping, float2 stores
#pragma unroll
    for (int mt = 0; mt < 2; mt++) {
        int r0 = bm + wm * 32 + mt * 16 + gid;
        int r1 = r0 + 8;
#pragma unroll
        for (int nt = 0; nt < 8; nt++) {
            int col = bn + wn * 64 + nt * 8 + tig * 2;
            if (r0 < M)
                *(float2*)(C + (size_t)r0 * N + col) = make_float2(acc[mt][nt][0], acc[mt][nt][1]);
            if (r1 < M)
                *(float2*)(C + (size_t)r1 * N + col) = make_float2(acc[mt][nt][2], acc[mt][nt][3]);
        }
    }
}

// ---------------------------------------------------------------------------
// Small-M fp32 SIMT GEMM for shallow levels (M <= 64). grid=(N/128, M),
// block=128. Full fp32 accuracy, high parallelism, low latency.
// ---------------------------------------------------------------------------
__global__ void __launch_bounds__(128) small_gemm_tn(
    const float* __restrict__ A, const float* __restrict__ B,
    float* __restrict__ C, int N, int K)
{
    __shared__ float Arow[FEAT_DIM];
    const int m = blockIdx.y;
    const int n = blockIdx.x * 128 + threadIdx.x;

    ((float4*)Arow)[threadIdx.x] = ((const float4*)(A + (size_t)m * K))[threadIdx.x];
    __syncthreads();

    const float4* Br = (const float4*)(B + (size_t)n * K);
    const float4* Ar = (const float4*)Arow;
    float s = 0.f;
#pragma unroll 8
    for (int i = 0; i < FEAT_DIM / 4; i++) {
        float4 b = Br[i];
        float4 a = Ar[i];
        s += a.x * b.x + a.y * b.y + a.z * b.z + a.w * b.w;
    }
    C[(size_t)m * N + n] = s;
}

// ---------------------------------------------------------------------------
// Per-level fused gate/elementwise kernel (unchanged, validated)
// ---------------------------------------------------------------------------
__device__ __forceinline__ float sigf(float x) { return 1.f / (1.f + expf(-x)); }
__device__ __forceinline__ float4 f4add(float4 a, float4 b) {
    return make_float4(a.x + b.x, a.y + b.y, a.z + b.z, a.w + b.w);
}

__global__ void __launch_bounds__(256) lstm_level_kernel(
    const float* __restrict__ iofux_b, const float* __restrict__ iofuh_b,
    const float* __restrict__ px_b, float* __restrict__ out,
    int start, int n, int hasPrev)
{
    int idx = blockIdx.x * 256 + threadIdx.x;
    int total = n * (H_DIM / 4);
    if (idx >= total) return;

    int j  = idx >> 7;
    int t4 = idx & 127;
    size_t g = (size_t)start + j;

    const float4* gx = (const float4*)(g_iofux + g * GATE5);
    float4 vi = gx[t4];
    float4 vo = gx[128 + t4];
    float4 vf = gx[256 + t4];
    float4 vu = gx[384 + t4];
    float4 vr = gx[512 + t4];

    float4 pc = make_float4(0.f, 0.f, 0.f, 0.f);
    if (hasPrev) {
        const float4* gh = (const float4*)(g_hh + (size_t)(j >> 1) * GATE5);
        vi = f4add(vi, gh[t4]);
        vo = f4add(vo, gh[128 + t4]);
        vf = f4add(vf, gh[256 + t4]);
        vu = f4add(vu, gh[384 + t4]);
        vr = f4add(vr, gh[512 + t4]);
        size_t parent = (g - 1) >> 1;
        pc = ((const float4*)g_c)[parent * 128 + t4];
    }

    const float4* bx = (const float4*)iofux_b;
    const float4* bh = (const float4*)iofuh_b;
    vi = f4add(vi, f4add(bx[t4],       bh[t4]));
    vo = f4add(vo, f4add(bx[128 + t4], bh[128 + t4]));
    vf = f4add(vf, f4add(bx[256 + t4], bh[256 + t4]));
    vu = f4add(vu, f4add(bx[384 + t4], bh[384 + t4]));
    vr = f4add(vr, f4add(bx[512 + t4], bh[512 + t4]));

    float4 px4 = f4add(((const float4*)g_px)[g * 128 + t4],
                       ((const float4*)px_b)[t4]);

    float4 c4, h4;
#define GATE(C) {                                                     \
        float i_ = sigf(vi.C); float o_ = sigf(vo.C);                 \
        float f_ = sigf(vf.C); float u_ = tanhf(vu.C);                \
        float r_ = sigf(vr.C);                                        \
        float c_ = i_ * u_ + f_ * pc.C;                               \
        float h_ = o_ * tanhf(c_);                                    \
        c4.C = c_; h4.C = r_ * h_ + (1.f - r_) * px4.C; }
    GATE(x) GATE(y) GATE(z) GATE(w)
#undef GATE

    ((float4*)g_c)[g * 128 + t4] = c4;
    ((float4*)out)[g * 128 + t4] = h4;
}

// ---------------------------------------------------------------------------
// kernel_launch
// ---------------------------------------------------------------------------
extern "C" void kernel_launch(void* const* d_in, const int* in_sizes, int n_in,
                              void* d_out, int out_size)
{
    const float* features = (const float*)d_in[0];
    const float* px_w     = (const float*)d_in[1];
    const float* px_b     = (const float*)d_in[2];
    const float* iofux_w  = (const float*)d_in[3];
    const float* iofux_b  = (const float*)d_in[4];
    const float* iofuh_w  = (const float*)d_in[5];
    const float* iofuh_b  = (const float*)d_in[6];
    float* out = (float*)d_out;

    float *iofux_p = nullptr, *px_p = nullptr, *hh_p = nullptr;
    cudaGetSymbolAddress((void**)&iofux_p, g_iofux);
    cudaGetSymbolAddress((void**)&px_p,    g_px);
    cudaGetSymbolAddress((void**)&hh_p,    g_hh);

    dim3 blk(256);

    // px = feats @ px_w.T   [N_NODES, 512]
    {
        dim3 grid(H_DIM / BN, (N_NODES + BM - 1) / BM);
        h16gemm_tn<<<grid, blk>>>(features, px_w, px_p, N_NODES, H_DIM, FEAT_DIM);
    }
    // iofux = feats @ iofux_w.T  [N_NODES, 2560]
    {
        dim3 grid(GATE5 / BN, (N_NODES + BM - 1) / BM);
        h16gemm_tn<<<grid, blk>>>(features, iofux_w, iofux_p, N_NODES, GATE5, FEAT_DIM);
    }

    for (int d = 0; d < DEPTH; d++) {
        int n = 1 << d;
        int start = n - 1;
        if (d > 0) {
            int Md = n >> 1;
            int startPrev = Md - 1;
            const float* Aprev = out + (size_t)startPrev * H_DIM;
            if (Md <= 64) {
                dim3 grid(GATE5 / 128, Md);
                small_gemm_tn<<<grid, 128>>>(Aprev, iofuh_w, hh_p, GATE5, FEAT_DIM);
            } else {
                dim3 grid(GATE5 / BN, (Md + BM - 1) / BM);
                h16gemm_tn<<<grid, blk>>>(Aprev, iofuh_w, hh_p, Md, GATE5, FEAT_DIM);
            }
        }
        int total = n * (H_DIM / 4);
        int nb = (total + 255) / 256;
        lstm_level_kernel<<<nb, blk>>>(iofux_b, iofuh_b, px_b, out,
                                       start, n, d > 0 ? 1 : 0);
    }
}

// round 6
// speedup vs baseline: 1.7746x; 1.0962x over previous
#include <cuda_runtime.h>
#include <cuda_fp16.h>
#include <math.h>
#include <stdint.h>

// Problem constants
#define FEAT_DIM 512
#define H_DIM    512
#define DEPTH    17
#define N_NODES  ((1 << DEPTH) - 1)   // 131071
#define GATE5    (5 * H_DIM)          // 2560
#define MAX_PREV (1 << (DEPTH - 2))   // 32768

// ---------------------------------------------------------------------------
// Scratch (static __device__ allocations; no cudaMalloc allowed)
// ---------------------------------------------------------------------------
__device__ float g_iofux[(size_t)N_NODES * GATE5];
__device__ float g_px   [(size_t)N_NODES * H_DIM];
__device__ float g_c    [(size_t)N_NODES * H_DIM];
__device__ float g_hh   [(size_t)MAX_PREV * GATE5];

__device__ __forceinline__ uint32_t smem_u32(const void* p) {
    uint32_t a;
    asm("{ .reg .u64 t; cvta.to.shared.u64 t, %1; cvt.u32.u64 %0, t; }" : "=r"(a) : "l"(p));
    return a;
}

// ---------------------------------------------------------------------------
// fp16 mma GEMM with ldmatrix fragment loads.
// C[M,N] = A[M,K] @ B[N,K]^T, fp32 in/out, fp32 accumulate.
// Block 128x128, BK=16, 256 thr = 8 warps, warp tile 32x64 (2x8 m16n8k16).
// SMEM row stride 40 halfs -> conflict-free LDSM phases.
// ---------------------------------------------------------------------------
#define BM 128
#define BN 128
#define BK 16
#define LH 40    // halfs per SMEM row

__device__ __forceinline__ void mma_f16(float c[4],
                                        uint32_t a0, uint32_t a1, uint32_t a2, uint32_t a3,
                                        uint32_t b0, uint32_t b1)
{
    asm volatile(
        "mma.sync.aligned.m16n8k16.row.col.f32.f16.f16.f32 "
        "{%0,%1,%2,%3}, {%4,%5,%6,%7}, {%8,%9}, {%0,%1,%2,%3};\n"
        : "+f"(c[0]), "+f"(c[1]), "+f"(c[2]), "+f"(c[3])
        : "r"(a0), "r"(a1), "r"(a2), "r"(a3), "r"(b0), "r"(b1));
}
#define LDSM_X4(r0, r1, r2, r3, addr) \
    asm volatile("ldmatrix.sync.aligned.m8n8.x4.shared.b16 {%0,%1,%2,%3}, [%4];" \
                 : "=r"(r0), "=r"(r1), "=r"(r2), "=r"(r3) : "r"(addr))

__device__ __forceinline__ uint32_t pack2h(float lo, float hi) {
    __half2 h = __floats2half2_rn(lo, hi);
    return *(uint32_t*)&h;
}

__global__ void __launch_bounds__(256, 2) h16gemm_tn(
    const float* __restrict__ A, const float* __restrict__ B,
    float* __restrict__ C, int M, int N, int K)
{
    __shared__ __align__(16) __half As[2][BM * LH];
    __shared__ __align__(16) __half Bs[2][BN * LH];

    const int tid  = threadIdx.x;
    const int lane = tid & 31;
    const int wid  = tid >> 5;
    const int wm   = wid & 3;        // warp row group (32 rows)
    const int wn   = wid >> 2;       // warp col group (64 cols)
    const int gid  = lane >> 2;
    const int tig  = lane & 3;
    const int bm   = blockIdx.y * BM;
    const int bn   = blockIdx.x * BN;

    // Loader: each thread owns 8 consecutive k of one row (2 float4 LDG)
    const int lrow = tid >> 1;             // 0..127
    const int lh   = (tid & 1) * 8;        // k offset 0 or 8

    int ar = bm + lrow; if (ar >= M) ar = M - 1;
    const float* Ap = A + (size_t)ar * K + lh;
    const float* Bp = B + (size_t)(bn + lrow) * K + lh;

    // ldmatrix per-lane addresses (buffer 0); advance by byte offset per buffer
    const uint32_t asB = smem_u32(&As[0][0]);
    const uint32_t bsB = smem_u32(&Bs[0][0]);
    const uint32_t ABUF = BM * LH * 2;     // bytes per A buffer
    const uint32_t BBUF = BN * LH * 2;
    // A: matrix row = m0 + (lane&15), k-half = (lane>>4)*8
    uint32_t aAdr[2];
#pragma unroll
    for (int mt = 0; mt < 2; mt++) {
        int m0 = wm * 32 + mt * 16;
        aAdr[mt] = asB + (((m0 + (lane & 15)) * LH) + (lane >> 4) * 8) * 2;
    }
    // B: pair p covers n-tiles 2p,2p+1: n = base + ((lane>>4)<<3) + (lane&7), kh = lane&8
    uint32_t bAdr[4];
#pragma unroll
    for (int p = 0; p < 4; p++) {
        int n0 = wn * 64 + p * 16 + ((lane >> 4) << 3) + (lane & 7);
        bAdr[p] = bsB + (n0 * LH + (lane & 8)) * 2;
    }

    float acc[2][8][4];
#pragma unroll
    for (int mt = 0; mt < 2; mt++)
#pragma unroll
        for (int nt = 0; nt < 8; nt++)
#pragma unroll
            for (int r = 0; r < 4; r++) acc[mt][nt][r] = 0.f;

    float4 fa0, fa1, fb0, fb1;
    auto prefetch = [&](int s) {
        const int k0 = s * BK;
        fa0 = *(const float4*)(Ap + k0);
        fa1 = *(const float4*)(Ap + k0 + 4);
        fb0 = *(const float4*)(Bp + k0);
        fb1 = *(const float4*)(Bp + k0 + 4);
    };
    auto store = [&](int b) {
        uint4 va;
        va.x = pack2h(fa0.x, fa0.y); va.y = pack2h(fa0.z, fa0.w);
        va.z = pack2h(fa1.x, fa1.y); va.w = pack2h(fa1.z, fa1.w);
        *(uint4*)&As[b][lrow * LH + lh] = va;
        uint4 vb;
        vb.x = pack2h(fb0.x, fb0.y); vb.y = pack2h(fb0.z, fb0.w);
        vb.z = pack2h(fb1.x, fb1.y); vb.w = pack2h(fb1.z, fb1.w);
        *(uint4*)&Bs[b][lrow * LH + lh] = vb;
    };

    prefetch(0);
    store(0);
    __syncthreads();

    const int nst = K / BK;          // 32
    for (int s = 0; s < nst; s++) {
        const int b = s & 1;
        const uint32_t ao = b * ABUF, bo = b * BBUF;
        if (s + 1 < nst) prefetch(s + 1);

        uint32_t af[2][4];
#pragma unroll
        for (int mt = 0; mt < 2; mt++)
            LDSM_X4(af[mt][0], af[mt][1], af[mt][2], af[mt][3], aAdr[mt] + ao);
        uint32_t bf[8][2];
#pragma unroll
        for (int p = 0; p < 4; p++)
            LDSM_X4(bf[2 * p][0], bf[2 * p][1], bf[2 * p + 1][0], bf[2 * p + 1][1],
                    bAdr[p] + bo);

#pragma unroll
        for (int mt = 0; mt < 2; mt++)
#pragma unroll
            for (int nt = 0; nt < 8; nt++)
                mma_f16(acc[mt][nt], af[mt][0], af[mt][1], af[mt][2], af[mt][3],
                        bf[nt][0], bf[nt][1]);

        if (s + 1 < nst) {
            store(b ^ 1);
            __syncthreads();
        }
    }

    // Epilogue: validated mapping, float2 stores
#pragma unroll
    for (int mt = 0; mt < 2; mt++) {
        int r0 = bm + wm * 32 + mt * 16 + gid;
        int r1 = r0 + 8;
#pragma unroll
        for (int nt = 0; nt < 8; nt++) {
            int col = bn + wn * 64 + nt * 8 + tig * 2;
            if (r0 < M)
                *(float2*)(C + (size_t)r0 * N + col) = make_float2(acc[mt][nt][0], acc[mt][nt][1]);
            if (r1 < M)
                *(float2*)(C + (size_t)r1 * N + col) = make_float2(acc[mt][nt][2], acc[mt][nt][3]);
        }
    }
}

// ---------------------------------------------------------------------------
// Small-M fp32 GEMM, high-parallelism: 16 cols/block x 16 lanes/col,
// shfl reduction. grid = (N/16, M). Full fp32 accuracy.
// ---------------------------------------------------------------------------
__global__ void __launch_bounds__(256) small_gemm_tn(
    const float* __restrict__ A, const float* __restrict__ B,
    float* __restrict__ C, int N, int K)
{
    __shared__ float Arow[FEAT_DIM];
    const int tid  = threadIdx.x;
    const int lane = tid & 31;
    const int wid  = tid >> 5;
    const int m    = blockIdx.y;

    if (tid < FEAT_DIM / 4)
        ((float4*)Arow)[tid] = ((const float4*)(A + (size_t)m * K))[tid];
    __syncthreads();

    const int col = blockIdx.x * 16 + wid * 2 + (lane >> 4);
    const int hl  = lane & 15;

    const float4* Br = (const float4*)(B + (size_t)col * K) + hl;
    const float4* Ar = (const float4*)Arow + hl;
    float s = 0.f;
#pragma unroll
    for (int i = 0; i < 8; i++) {              // K/ (16*4) = 8
        float4 b = Br[i * 16];
        float4 a = Ar[i * 16];
        s += a.x * b.x + a.y * b.y + a.z * b.z + a.w * b.w;
    }
#pragma unroll
    for (int off = 8; off >= 1; off >>= 1)
        s += __shfl_xor_sync(0xffffffff, s, off);
    if (hl == 0)
        C[(size_t)m * N + col] = s;
}

// ---------------------------------------------------------------------------
// Per-level fused gate/elementwise kernel (unchanged, validated)
// ---------------------------------------------------------------------------
__device__ __forceinline__ float sigf(float x) { return 1.f / (1.f + expf(-x)); }
__device__ __forceinline__ float4 f4add(float4 a, float4 b) {
    return make_float4(a.x + b.x, a.y + b.y, a.z + b.z, a.w + b.w);
}

__global__ void __launch_bounds__(256) lstm_level_kernel(
    const float* __restrict__ iofux_b, const float* __restrict__ iofuh_b,
    const float* __restrict__ px_b, float* __restrict__ out,
    int start, int n, int hasPrev)
{
    int idx = blockIdx.x * 256 + threadIdx.x;
    int total = n * (H_DIM / 4);
    if (idx >= total) return;

    int j  = idx >> 7;
    int t4 = idx & 127;
    size_t g = (size_t)start + j;

    const float4* gx = (const float4*)(g_iofux + g * GATE5);
    float4 vi = gx[t4];
    float4 vo = gx[128 + t4];
    float4 vf = gx[256 + t4];
    float4 vu = gx[384 + t4];
    float4 vr = gx[512 + t4];

    float4 pc = make_float4(0.f, 0.f, 0.f, 0.f);
    if (hasPrev) {
        const float4* gh = (const float4*)(g_hh + (size_t)(j >> 1) * GATE5);
        vi = f4add(vi, gh[t4]);
        vo = f4add(vo, gh[128 + t4]);
        vf = f4add(vf, gh[256 + t4]);
        vu = f4add(vu, gh[384 + t4]);
        vr = f4add(vr, gh[512 + t4]);
        size_t parent = (g - 1) >> 1;
        pc = ((const float4*)g_c)[parent * 128 + t4];
    }

    const float4* bx = (const float4*)iofux_b;
    const float4* bh = (const float4*)iofuh_b;
    vi = f4add(vi, f4add(bx[t4],       bh[t4]));
    vo = f4add(vo, f4add(bx[128 + t4], bh[128 + t4]));
    vf = f4add(vf, f4add(bx[256 + t4], bh[256 + t4]));
    vu = f4add(vu, f4add(bx[384 + t4], bh[384 + t4]));
    vr = f4add(vr, f4add(bx[512 + t4], bh[512 + t4]));

    float4 px4 = f4add(((const float4*)g_px)[g * 128 + t4],
                       ((const float4*)px_b)[t4]);

    float4 c4, h4;
#define GATE(C) {                                                     \
        float i_ = sigf(vi.C); float o_ = sigf(vo.C);                 \
        float f_ = sigf(vf.C); float u_ = tanhf(vu.C);                \
        float r_ = sigf(vr.C);                                        \
        float c_ = i_ * u_ + f_ * pc.C;                               \
        float h_ = o_ * tanhf(c_);                                    \
        c4.C = c_; h4.C = r_ * h_ + (1.f - r_) * px4.C; }
    GATE(x) GATE(y) GATE(z) GATE(w)
#undef GATE

    ((float4*)g_c)[g * 128 + t4] = c4;
    ((float4*)out)[g * 128 + t4] = h4;
}

// ---------------------------------------------------------------------------
// kernel_launch
// ---------------------------------------------------------------------------
extern "C" void kernel_launch(void* const* d_in, const int* in_sizes, int n_in,
                              void* d_out, int out_size)
{
    const float* features = (const float*)d_in[0];
    const float* px_w     = (const float*)d_in[1];
    const float* px_b     = (const float*)d_in[2];
    const float* iofux_w  = (const float*)d_in[3];
    const float* iofux_b  = (const float*)d_in[4];
    const float* iofuh_w  = (const float*)d_in[5];
    const float* iofuh_b  = (const float*)d_in[6];
    float* out = (float*)d_out;

    float *iofux_p = nullptr, *px_p = nullptr, *hh_p = nullptr;
    cudaGetSymbolAddress((void**)&iofux_p, g_iofux);
    cudaGetSymbolAddress((void**)&px_p,    g_px);
    cudaGetSymbolAddress((void**)&hh_p,    g_hh);

    dim3 blk(256);

    // px = feats @ px_w.T   [N_NODES, 512]
    {
        dim3 grid(H_DIM / BN, (N_NODES + BM - 1) / BM);
        h16gemm_tn<<<grid, blk>>>(features, px_w, px_p, N_NODES, H_DIM, FEAT_DIM);
    }
    // iofux = feats @ iofux_w.T  [N_NODES, 2560]
    {
        dim3 grid(GATE5 / BN, (N_NODES + BM - 1) / BM);
        h16gemm_tn<<<grid, blk>>>(features, iofux_w, iofux_p, N_NODES, GATE5, FEAT_DIM);
    }

    for (int d = 0; d < DEPTH; d++) {
        int n = 1 << d;
        int start = n - 1;
        if (d > 0) {
            int Md = n >> 1;
            int startPrev = Md - 1;
            const float* Aprev = out + (size_t)startPrev * H_DIM;
            if (Md <= 64) {
                dim3 grid(GATE5 / 16, Md);
                small_gemm_tn<<<grid, 256>>>(Aprev, iofuh_w, hh_p, GATE5, FEAT_DIM);
            } else {
                dim3 grid(GATE5 / BN, (Md + BM - 1) / BM);
                h16gemm_tn<<<grid, blk>>>(Aprev, iofuh_w, hh_p, Md, GATE5, FEAT_DIM);
            }
        }
        int total = n * (H_DIM / 4);
        int nb = (total + 255) / 256;
        lstm_level_kernel<<<nb, blk>>>(iofux_b, iofuh_b, px_b, out,
                                       start, n, d > 0 ? 1 : 0);
    }
}